// round 15
// baseline (speedup 1.0000x reference)
#include <cuda_runtime.h>
#include <cuda_bf16.h>

// ---------------------------------------------------------------------------
// ParamMakeFeature: FUSED single kernel.
// Each block first computes its batch's folded params (W1R = W1*R^T, irrep
// D-blocks via Kronecker powers + Q projections, M3 = Dblk*W3, c3 = Dblk*b3)
// directly into shared memory (~10K FLOPs, 7 barrier phases), replacing the
// separate precompute kernel + g_params round-trip + launch boundary
// (~4.5-5.9us measured across R7-R14).
//
// Main body is the R7 validated optimum (43.4us): weights as SCALARS
// (4 per LDS.128); f32x2 pairs over adjacent FEATURES of one point; weight
// pairs alias loaded float4 registers; 4 points/thread; 128-thr blocks,
// bounds(128,3), regs~168. Occupancy caps (R8/R11/R12) proven to spill;
// all loops fully unrolled (R4: runtime-indexed arrays demote to local).
//
// x LDGs issue at the very top: their DRAM latency overlaps the param phases.
// ---------------------------------------------------------------------------

typedef unsigned long long u64;

#define FEAT 15

// per-batch scalar params in smem, 16 floats per row:
//  rows 0-2 : stage1T row k: col f = W1R[f][k]   (col 15 = 0)
//  row  3   : b1[f]
//  rows 4-18: stage2T row f: col g = W2[g][f]    (col 15 = 0)
//  row  19  : b2[g]
//  rows 20-34: stage3T row f: col p = M3[p][f]
//  row  35  : c3[p]
#define S1_ROW 0
#define S2_ROW 4
#define S3_ROW 20
#define PAR_F 576     // 36 rows * 16 floats

__device__ __forceinline__ u64 pk2(float lo, float hi) {
    u64 r; asm("mov.b64 %0, {%1,%2};" : "=l"(r) : "f"(lo), "f"(hi)); return r;
}
__device__ __forceinline__ void upk2(u64 v, float& lo, float& hi) {
    asm("mov.b64 {%0,%1}, %2;" : "=f"(lo), "=f"(hi) : "l"(v));
}
__device__ __forceinline__ u64 ffma2(u64 a, u64 b, u64 c) {
    u64 d; asm("fma.rn.f32x2 %0, %1, %2, %3;" : "=l"(d) : "l"(a), "l"(b), "l"(c));
    return d;
}

// load one 16-float row as 8 feature-pairs (pairs alias the loaded quads)
__device__ __forceinline__ void load_row(u64 wp[8], const float4* q) {
    float4 q0 = q[0], q1 = q[1], q2 = q[2], q3 = q[3];
    wp[0] = pk2(q0.x, q0.y); wp[1] = pk2(q0.z, q0.w);
    wp[2] = pk2(q1.x, q1.y); wp[3] = pk2(q1.z, q1.w);
    wp[4] = pk2(q2.x, q2.y); wp[5] = pk2(q2.z, q2.w);
    wp[6] = pk2(q3.x, q3.y); wp[7] = pk2(q3.z, q3.w);
}

#define THREADS 128

__global__ __launch_bounds__(THREADS, 3)
void mf_fused_kernel(const float* __restrict__ x, float* __restrict__ out, int N,
                     const float* __restrict__ R_all,
                     const float* __restrict__ W1, const float* __restrict__ b1,
                     const float* __restrict__ W2, const float* __restrict__ b2,
                     const float* __restrict__ W3, const float* __restrict__ b3,
                     const float* __restrict__ Q1, const float* __restrict__ Q2,
                     const float* __restrict__ Q3)
{
    const int b = blockIdx.y;
    const int tid = threadIdx.x;
    const int t = blockIdx.x * THREADS + tid;
    const int quads = N >> 2;

    const float* xb = x + (size_t)b * 3 * N;
    float* __restrict__ ob = out + (size_t)b * FEAT * N;

    // ---- x loads FIRST: their DRAM latency overlaps the param phases ----
    const bool main_lane = (t < quads);
    const int tl = main_lane ? t : 0;
    float4 a0 = __ldcs((const float4*)(xb                 ) + tl);
    float4 a1 = __ldcs((const float4*)(xb + N             ) + tl);
    float4 a2 = __ldcs((const float4*)(xb + 2 * (size_t)N ) + tl);

    // ---- param scratch + final param block in smem ----
    __shared__ __align__(16) float swf[PAR_F];
    __shared__ float R[9];
    __shared__ float K2[81];
    __shared__ float K3[729];
    __shared__ float E2s[45];     // [i*5+q], i<9
    __shared__ float E3s[189];    // [u*7+q], u<27
    __shared__ float D1s[9], D2s[25], D3s[49];
    __shared__ float M3s[225], c3s[15], W1Rs[45];

    if (tid < 9) R[tid] = R_all[b * 9 + tid];
    __syncthreads();                                    // B0: R ready

    // P1: K2 = R kron R ; W1R = W1 * R^T
    if (tid < 81) {
        int row = tid / 9, col = tid % 9;
        int i = row / 3, k = row % 3, j = col / 3, l = col % 3;
        K2[tid] = R[i * 3 + j] * R[k * 3 + l];
    } else if (tid < 126) {
        int t2 = tid - 81, f = t2 / 3, j = t2 % 3;
        float s = 0.f;
        for (int i = 0; i < 3; i++) s += W1[f * 3 + i] * R[j * 3 + i];
        W1Rs[f * 3 + j] = s;
    }
    __syncthreads();                                    // B1: K2, W1R ready

    // P2: K3 = K2 kron R ; E2 = K2 * Q2^T ; D1 = Q1 R Q1^T
    for (int idx = tid; idx < 729; idx += THREADS) {
        int row = idx / 27, col = idx % 27;
        int a = row / 3, m = row % 3, bb = col / 3, nn = col % 3;
        K3[idx] = K2[a * 9 + bb] * R[m * 3 + nn];
    }
    if (tid < 45) {
        int i = tid / 5, q = tid % 5;
        float s = 0.f;
        for (int j = 0; j < 9; j++) s += K2[i * 9 + j] * Q2[q * 9 + j];
        E2s[tid] = s;
    } else if (tid >= 64 && tid < 73) {
        int t2 = tid - 64, p = t2 / 3, q = t2 % 3;
        float s = 0.f;
        for (int i = 0; i < 3; i++)
            for (int j = 0; j < 3; j++)
                s += Q1[p * 3 + i] * R[i * 3 + j] * Q1[q * 3 + j];
        D1s[p * 3 + q] = s;
    }
    __syncthreads();                                    // B2: K3, E2, D1 ready

    // P3: E3 = K3 * Q3^T ; D2 = Q2 * E2
    for (int idx = tid; idx < 189; idx += THREADS) {
        int u = idx / 7, q = idx % 7;
        float s = 0.f;
        for (int v = 0; v < 27; v++) s += K3[u * 27 + v] * Q3[q * 27 + v];
        E3s[idx] = s;
    }
    if (tid < 25) {
        int p = tid / 5, q = tid % 5;
        float s = 0.f;
        for (int i = 0; i < 9; i++) s += Q2[p * 9 + i] * E2s[i * 5 + q];
        D2s[tid] = s;
    }
    __syncthreads();                                    // B3: E3, D2 ready

    // P4: D3 = Q3 * E3
    if (tid < 49) {
        int p = tid / 7, q = tid % 7;
        float s = 0.f;
        for (int u = 0; u < 27; u++) s += Q3[p * 27 + u] * E3s[u * 7 + q];
        D3s[tid] = s;
    }
    __syncthreads();                                    // B4: D3 ready

    // P5: M3 = blockdiag(D1,D2,D3) * W3 ; c3 = blockdiag * b3
    for (int idx = tid; idx < 225; idx += THREADS) {
        int p = idx / 15, f = idx % 15;
        float s = 0.f;
        if (p < 3)       { for (int q = 0; q < 3; q++) s += D1s[p * 3 + q]       * W3[q * 15 + f]; }
        else if (p < 8)  { for (int q = 0; q < 5; q++) s += D2s[(p - 3) * 5 + q] * W3[(3 + q) * 15 + f]; }
        else             { for (int q = 0; q < 7; q++) s += D3s[(p - 8) * 7 + q] * W3[(8 + q) * 15 + f]; }
        M3s[idx] = s;
    }
    if (tid < 15) {
        int p = tid;
        float s = 0.f;
        if (p < 3)       { for (int q = 0; q < 3; q++) s += D1s[p * 3 + q]       * b3[q]; }
        else if (p < 8)  { for (int q = 0; q < 5; q++) s += D2s[(p - 3) * 5 + q] * b3[3 + q]; }
        else             { for (int q = 0; q < 7; q++) s += D3s[(p - 8) * 7 + q] * b3[8 + q]; }
        c3s[p] = s;
    }
    __syncthreads();                                    // B5: M3, c3 ready

    // P6: assemble final scalar transposed padded layout
    for (int idx = tid; idx < PAR_F; idx += THREADS) {
        float v = 0.f;
        if (idx < S2_ROW * 16) {
            int k = idx >> 4, f = idx & 15;
            if (f < 15) v = (k < 3) ? W1Rs[f * 3 + k] : b1[f];
        } else if (idx < S3_ROW * 16) {
            int r = idx - S2_ROW * 16, f = r >> 4, g = r & 15;
            if (g < 15) v = (f < 15) ? W2[g * 15 + f] : b2[g];
        } else {
            int r = idx - S3_ROW * 16, f = r >> 4, p = r & 15;
            if (p < 15) v = (f < 15) ? M3s[p * 15 + f] : c3s[p];
        }
        swf[idx] = v;
    }
    __syncthreads();                                    // B6: params ready

    // ======================= R7 main body (verbatim) =======================
    const float4* swq = (const float4*)swf;

    if (main_lane) {
        float xc0[4] = { a0.x, a0.y, a0.z, a0.w };
        float xc1[4] = { a1.x, a1.y, a1.z, a1.w };
        float xc2[4] = { a2.x, a2.y, a2.z, a2.w };

        // ---- stage 1: acc[p][j] = (h1[2j], h1[2j+1]) ----
        u64 acc1[4][8];
        {
            u64 bp[8]; load_row(bp, swq + (S1_ROW + 3) * 4);
            u64 wp[8];
            load_row(wp, swq + (S1_ROW + 0) * 4);
#pragma unroll
            for (int p = 0; p < 4; p++) {
                u64 xd = pk2(xc0[p], xc0[p]);
#pragma unroll
                for (int j = 0; j < 8; j++) acc1[p][j] = ffma2(xd, wp[j], bp[j]);
            }
            load_row(wp, swq + (S1_ROW + 1) * 4);
#pragma unroll
            for (int p = 0; p < 4; p++) {
                u64 xd = pk2(xc1[p], xc1[p]);
#pragma unroll
                for (int j = 0; j < 8; j++) acc1[p][j] = ffma2(xd, wp[j], acc1[p][j]);
            }
            load_row(wp, swq + (S1_ROW + 2) * 4);
#pragma unroll
            for (int p = 0; p < 4; p++) {
                u64 xd = pk2(xc2[p], xc2[p]);
#pragma unroll
                for (int j = 0; j < 8; j++) acc1[p][j] = ffma2(xd, wp[j], acc1[p][j]);
            }
        }

        // relu -> scalar h1[p][f]
        float h1[4][FEAT];
#pragma unroll
        for (int p = 0; p < 4; p++) {
#pragma unroll
            for (int j = 0; j < 7; j++) {
                float lo, hi; upk2(acc1[p][j], lo, hi);
                h1[p][2 * j]     = fmaxf(lo, 0.f);
                h1[p][2 * j + 1] = fmaxf(hi, 0.f);
            }
            { float lo, hi; upk2(acc1[p][7], lo, hi); h1[p][14] = fmaxf(lo, 0.f); (void)hi; }
        }

        // ---- stage 2: acc2[p][j] = (h2[2j], h2[2j+1]) ----
        u64 acc2[4][8];
        {
            u64 bp[8]; load_row(bp, swq + (S2_ROW + 15) * 4);
            u64 wp[8];
            load_row(wp, swq + (S2_ROW + 0) * 4);
#pragma unroll
            for (int p = 0; p < 4; p++) {
                u64 md = pk2(h1[p][0], h1[p][0]);
#pragma unroll
                for (int j = 0; j < 8; j++) acc2[p][j] = ffma2(md, wp[j], bp[j]);
            }
#pragma unroll
            for (int f = 1; f < FEAT; f++) {
                load_row(wp, swq + (S2_ROW + f) * 4);
#pragma unroll
                for (int p = 0; p < 4; p++) {
                    u64 md = pk2(h1[p][f], h1[p][f]);
#pragma unroll
                    for (int j = 0; j < 8; j++) acc2[p][j] = ffma2(md, wp[j], acc2[p][j]);
                }
            }
        }

        // relu -> scalar h2[p][f]
        float h2[4][FEAT];
#pragma unroll
        for (int p = 0; p < 4; p++) {
#pragma unroll
            for (int j = 0; j < 7; j++) {
                float lo, hi; upk2(acc2[p][j], lo, hi);
                h2[p][2 * j]     = fmaxf(lo, 0.f);
                h2[p][2 * j + 1] = fmaxf(hi, 0.f);
            }
            { float lo, hi; upk2(acc2[p][7], lo, hi); h2[p][14] = fmaxf(lo, 0.f); (void)hi; }
        }

        // ---- stage 3: acc3[p][j] = (y[2j], y[2j+1]) ----
        u64 acc3[4][8];
        {
            u64 bp[8]; load_row(bp, swq + (S3_ROW + 15) * 4);
            u64 wp[8];
            load_row(wp, swq + (S3_ROW + 0) * 4);
#pragma unroll
            for (int p = 0; p < 4; p++) {
                u64 md = pk2(h2[p][0], h2[p][0]);
#pragma unroll
                for (int j = 0; j < 8; j++) acc3[p][j] = ffma2(md, wp[j], bp[j]);
            }
#pragma unroll
            for (int f = 1; f < FEAT; f++) {
                load_row(wp, swq + (S3_ROW + f) * 4);
#pragma unroll
                for (int p = 0; p < 4; p++) {
                    u64 md = pk2(h2[p][f], h2[p][f]);
#pragma unroll
                    for (int j = 0; j < 8; j++) acc3[p][j] = ffma2(md, wp[j], acc3[p][j]);
                }
            }
        }

        // ---- store: transpose in-register, one float4 per feature row ----
#pragma unroll
        for (int pp = 0; pp < FEAT; pp++) {
            const int j = pp >> 1;
            float4 st;
            {
                float lo, hi;
                upk2(acc3[0][j], lo, hi); st.x = (pp & 1) ? hi : lo;
                upk2(acc3[1][j], lo, hi); st.y = (pp & 1) ? hi : lo;
                upk2(acc3[2][j], lo, hi); st.z = (pp & 1) ? hi : lo;
                upk2(acc3[3][j], lo, hi); st.w = (pp & 1) ? hi : lo;
            }
            __stcs((float4*)(ob + (size_t)pp * N) + t, st);
        }
    } else {
        // scalar tail for N % 4 leftover points
        const int rem = N & 3;
        const int tp = t - quads;
        if (tp < rem) {
            const int p = (quads << 2) + tp;
            float xv[3] = { xb[p], xb[N + p], xb[2 * (size_t)N + p] };
            float h1[FEAT], h2[FEAT], o[FEAT];
            for (int f = 0; f < FEAT; f++) h1[f] = swf[(S1_ROW + 3) * 16 + f];
            for (int k = 0; k < 3; k++)
                for (int f = 0; f < FEAT; f++)
                    h1[f] += xv[k] * swf[(S1_ROW + k) * 16 + f];
            for (int f = 0; f < FEAT; f++) h1[f] = fmaxf(h1[f], 0.f);

            for (int g = 0; g < FEAT; g++) h2[g] = swf[(S2_ROW + 15) * 16 + g];
            for (int f = 0; f < FEAT; f++)
                for (int g = 0; g < FEAT; g++)
                    h2[g] += h1[f] * swf[(S2_ROW + f) * 16 + g];
            for (int g = 0; g < FEAT; g++) h2[g] = fmaxf(h2[g], 0.f);

            for (int pp = 0; pp < FEAT; pp++) o[pp] = swf[(S3_ROW + 15) * 16 + pp];
            for (int f = 0; f < FEAT; f++)
                for (int pp = 0; pp < FEAT; pp++)
                    o[pp] += h2[f] * swf[(S3_ROW + f) * 16 + pp];
            for (int pp = 0; pp < FEAT; pp++)
                ob[(size_t)pp * N + p] = o[pp];
        }
    }
}

// ---------------------------------------------------------------------------
extern "C" void kernel_launch(void* const* d_in, const int* in_sizes, int n_in,
                              void* d_out, int out_size)
{
    const float* x  = (const float*)d_in[0];
    const float* R  = (const float*)d_in[1];
    const float* W1 = (const float*)d_in[2];
    const float* b1 = (const float*)d_in[3];
    const float* W2 = (const float*)d_in[4];
    const float* b2 = (const float*)d_in[5];
    const float* W3 = (const float*)d_in[6];
    const float* b3 = (const float*)d_in[7];
    const float* Q1 = (const float*)d_in[8];
    const float* Q2 = (const float*)d_in[9];
    const float* Q3 = (const float*)d_in[10];

    int B = in_sizes[1] / 9;
    int N = in_sizes[0] / (3 * B);

    int quads = N >> 2;
    int gx = (quads + THREADS - 1) / THREADS;
    if (N & 3) gx += 1;   // guarantee spare threads for the scalar tail
    dim3 grid(gx, B);
    mf_fused_kernel<<<grid, THREADS>>>(x, (float*)d_out, N,
                                       R, W1, b1, W2, b2, W3, b3, Q1, Q2, Q3);
}

// round 16
// speedup vs baseline: 1.5354x; 1.5354x over previous
#include <cuda_runtime.h>
#include <cuda_bf16.h>

// ---------------------------------------------------------------------------
// ParamMakeFeature: fold rotation into MLP weights, then run a packed-f32x2
// 3->15->15->15 MLP, 4 points per thread.
//
// FINAL (R7, validated best = 49.3us total / 43.4us main):
//  - weights stored as SCALARS in smem (4 per LDS.128) — halves the LDS
//    instruction stream vs duplicated-pair layout (R7 vs R3-R6: L1 63->46%)
//  - f32x2 pairs run over adjacent FEATURES of one point; weight pairs alias
//    loaded float4 registers; per-f multiplier (h_f,h_f) costs MOVs on the
//    under-used ALU pipe
//  - 4 points/thread, float4 LDG/STG, __ldcs/__stcs streaming hints
//  - 128-thr blocks, __launch_bounds__(128,3): regs~168 is STRUCTURAL
//    (h-live-across-stage + accs); R8/R11/R12 proved caps below ~160 spill
//  - all loops fully unrolled (R4: runtime-indexed arrays demote to local)
//  - separate tiny precompute kernel; PDL (R13/R14) and fusion (R15) measured
//    net-neutral / strongly negative, so plain two-launch form is kept.
// ---------------------------------------------------------------------------

typedef unsigned long long u64;

#define FEAT 15
#define MAXB 32

// per-batch scalar params, 16 floats per row:
//  rows 0-2 : stage1T row k: col f = W1R[f][k]   (col 15 = 0)
//  row  3   : b1[f]
//  rows 4-18: stage2T row f: col g = W2[g][f]    (col 15 = 0)
//  row  19  : b2[g]
//  rows 20-34: stage3T row f: col p = M3[p][f]
//  row  35  : c3[p]
#define S1_ROW 0
#define S2_ROW 4
#define S3_ROW 20
#define PAR_F 576     // 36 rows * 16 floats

__device__ float g_params[MAXB * PAR_F];

__device__ __forceinline__ u64 pk2(float lo, float hi) {
    u64 r; asm("mov.b64 %0, {%1,%2};" : "=l"(r) : "f"(lo), "f"(hi)); return r;
}
__device__ __forceinline__ void upk2(u64 v, float& lo, float& hi) {
    asm("mov.b64 {%0,%1}, %2;" : "=f"(lo), "=f"(hi) : "l"(v));
}
__device__ __forceinline__ u64 ffma2(u64 a, u64 b, u64 c) {
    u64 d; asm("fma.rn.f32x2 %0, %1, %2, %3;" : "=l"(d) : "l"(a), "l"(b), "l"(c));
    return d;
}

// load one 16-float row as 8 feature-pairs (pairs alias the loaded quads)
__device__ __forceinline__ void load_row(u64 wp[8], const float4* q) {
    float4 q0 = q[0], q1 = q[1], q2 = q[2], q3 = q[3];
    wp[0] = pk2(q0.x, q0.y); wp[1] = pk2(q0.z, q0.w);
    wp[2] = pk2(q1.x, q1.y); wp[3] = pk2(q1.z, q1.w);
    wp[4] = pk2(q2.x, q2.y); wp[5] = pk2(q2.z, q2.w);
    wp[6] = pk2(q3.x, q3.y); wp[7] = pk2(q3.z, q3.w);
}

// ---------------------------------------------------------------------------
// Precompute kernel: one block per batch. Builds W1R = W1*R^T, D-blocks,
// M3 = Dblk*W3, c3 = Dblk*b3; writes SCALAR transposed padded layout.
// ---------------------------------------------------------------------------
__global__ void precompute_kernel(
    const float* __restrict__ R_all,
    const float* __restrict__ W1, const float* __restrict__ b1,
    const float* __restrict__ W2, const float* __restrict__ b2,
    const float* __restrict__ W3, const float* __restrict__ b3,
    const float* __restrict__ Q1, const float* __restrict__ Q2,
    const float* __restrict__ Q3)
{
    const int b = blockIdx.x;
    const int tid = threadIdx.x;

    __shared__ float R[9];
    __shared__ float K2[81];
    __shared__ float K3[729];
    __shared__ float E2[9][5];
    __shared__ float E3[27][7];
    __shared__ float D1[3][3], D2[5][5], D3[7][7];
    __shared__ float M3[15][15], c3[15], W1Rs[15][3];

    if (tid < 9) R[tid] = R_all[b * 9 + tid];
    __syncthreads();

    if (tid < 81) {
        int row = tid / 9, col = tid % 9;
        int i = row / 3, k = row % 3, j = col / 3, l = col % 3;
        K2[tid] = R[i * 3 + j] * R[k * 3 + l];
    } else if (tid >= 96 && tid < 105) {
        int t = tid - 96, p = t / 3, q = t % 3;
        float s = 0.f;
        for (int i = 0; i < 3; i++)
            for (int j = 0; j < 3; j++)
                s += Q1[p * 3 + i] * R[i * 3 + j] * Q1[q * 3 + j];
        D1[p][q] = s;
    } else if (tid >= 112 && tid < 157) {
        int t = tid - 112, f = t / 3, j = t % 3;
        float s = 0.f;
        for (int i = 0; i < 3; i++) s += W1[f * 3 + i] * R[j * 3 + i];
        W1Rs[f][j] = s;
    }
    __syncthreads();

    if (tid < 45) {
        int i = tid / 5, q = tid % 5;
        float s = 0.f;
        for (int j = 0; j < 9; j++) s += K2[i * 9 + j] * Q2[q * 9 + j];
        E2[i][q] = s;
    }
    for (int idx = tid; idx < 729; idx += blockDim.x) {
        int row = idx / 27, col = idx % 27;
        int a = row / 3, m = row % 3, bb = col / 3, nn = col % 3;
        K3[idx] = K2[a * 9 + bb] * R[m * 3 + nn];
    }
    __syncthreads();

    if (tid < 25) {
        int p = tid / 5, q = tid % 5;
        float s = 0.f;
        for (int i = 0; i < 9; i++) s += Q2[p * 9 + i] * E2[i][q];
        D2[p][q] = s;
    } else if (tid >= 32 && tid < 32 + 189) {
        int t = tid - 32, u = t / 7, q = t % 7;
        float s = 0.f;
        for (int v = 0; v < 27; v++) s += K3[u * 27 + v] * Q3[q * 27 + v];
        E3[u][q] = s;
    }
    __syncthreads();

    if (tid < 49) {
        int p = tid / 7, q = tid % 7;
        float s = 0.f;
        for (int u = 0; u < 27; u++) s += Q3[p * 27 + u] * E3[u][q];
        D3[p][q] = s;
    }
    __syncthreads();

    if (tid < 225) {
        int p = tid / 15, f = tid % 15;
        float s = 0.f;
        if (p < 3)       { for (int q = 0; q < 3; q++) s += D1[p][q]     * W3[q * 15 + f]; }
        else if (p < 8)  { for (int q = 0; q < 5; q++) s += D2[p - 3][q] * W3[(3 + q) * 15 + f]; }
        else             { for (int q = 0; q < 7; q++) s += D3[p - 8][q] * W3[(8 + q) * 15 + f]; }
        M3[p][f] = s;
    } else if (tid < 240) {
        int p = tid - 225;
        float s = 0.f;
        if (p < 3)       { for (int q = 0; q < 3; q++) s += D1[p][q]     * b3[q]; }
        else if (p < 8)  { for (int q = 0; q < 5; q++) s += D2[p - 3][q] * b3[3 + q]; }
        else             { for (int q = 0; q < 7; q++) s += D3[p - 8][q] * b3[8 + q]; }
        c3[p] = s;
    }
    __syncthreads();

    // write scalar transposed padded layout
    float* dst = g_params + (size_t)b * PAR_F;
    for (int idx = tid; idx < PAR_F; idx += blockDim.x) {
        float v = 0.f;
        if (idx < S2_ROW * 16) {
            int k = idx >> 4, f = idx & 15;
            if (f < 15) v = (k < 3) ? W1Rs[f][k] : b1[f];
        } else if (idx < S3_ROW * 16) {
            int r = idx - S2_ROW * 16, f = r >> 4, g = r & 15;
            if (g < 15) v = (f < 15) ? W2[g * 15 + f] : b2[g];
        } else {
            int r = idx - S3_ROW * 16, f = r >> 4, p = r & 15;
            if (p < 15) v = (f < 15) ? M3[p][f] : c3[p];
        }
        dst[idx] = v;
    }
}

// ---------------------------------------------------------------------------
// Main kernel: 4 points per thread, feature-paired f32x2 accumulators.
// ---------------------------------------------------------------------------
#define THREADS 128

__global__ __launch_bounds__(THREADS, 3)
void mf_main_kernel(const float* __restrict__ x, float* __restrict__ out, int N)
{
    const int b = blockIdx.y;
    __shared__ __align__(16) float swf[PAR_F];
    {
        const float4* src = (const float4*)(g_params + (size_t)b * PAR_F);
        float4* dstq = (float4*)swf;
        for (int i = threadIdx.x; i < PAR_F / 4; i += THREADS) dstq[i] = src[i];
    }
    __syncthreads();

    const int t = blockIdx.x * THREADS + threadIdx.x;
    const int quads = N >> 2;

    const float* xb = x + (size_t)b * 3 * N;
    float* __restrict__ ob = out + (size_t)b * FEAT * N;
    const float4* swq = (const float4*)swf;

    if (t < quads) {
        float4 a0 = __ldcs((const float4*)(xb                 ) + t);
        float4 a1 = __ldcs((const float4*)(xb + N             ) + t);
        float4 a2 = __ldcs((const float4*)(xb + 2 * (size_t)N ) + t);
        float xc0[4] = { a0.x, a0.y, a0.z, a0.w };
        float xc1[4] = { a1.x, a1.y, a1.z, a1.w };
        float xc2[4] = { a2.x, a2.y, a2.z, a2.w };

        // ---- stage 1: acc[p][j] = (h1[2j], h1[2j+1]) ----
        u64 acc1[4][8];
        {
            u64 bp[8]; load_row(bp, swq + (S1_ROW + 3) * 4);
            u64 wp[8];
            load_row(wp, swq + (S1_ROW + 0) * 4);
#pragma unroll
            for (int p = 0; p < 4; p++) {
                u64 xd = pk2(xc0[p], xc0[p]);
#pragma unroll
                for (int j = 0; j < 8; j++) acc1[p][j] = ffma2(xd, wp[j], bp[j]);
            }
            load_row(wp, swq + (S1_ROW + 1) * 4);
#pragma unroll
            for (int p = 0; p < 4; p++) {
                u64 xd = pk2(xc1[p], xc1[p]);
#pragma unroll
                for (int j = 0; j < 8; j++) acc1[p][j] = ffma2(xd, wp[j], acc1[p][j]);
            }
            load_row(wp, swq + (S1_ROW + 2) * 4);
#pragma unroll
            for (int p = 0; p < 4; p++) {
                u64 xd = pk2(xc2[p], xc2[p]);
#pragma unroll
                for (int j = 0; j < 8; j++) acc1[p][j] = ffma2(xd, wp[j], acc1[p][j]);
            }
        }

        // relu -> scalar h1[p][f]
        float h1[4][FEAT];
#pragma unroll
        for (int p = 0; p < 4; p++) {
#pragma unroll
            for (int j = 0; j < 7; j++) {
                float lo, hi; upk2(acc1[p][j], lo, hi);
                h1[p][2 * j]     = fmaxf(lo, 0.f);
                h1[p][2 * j + 1] = fmaxf(hi, 0.f);
            }
            { float lo, hi; upk2(acc1[p][7], lo, hi); h1[p][14] = fmaxf(lo, 0.f); (void)hi; }
        }

        // ---- stage 2: acc2[p][j] = (h2[2j], h2[2j+1]) ----
        u64 acc2[4][8];
        {
            u64 bp[8]; load_row(bp, swq + (S2_ROW + 15) * 4);
            u64 wp[8];
            load_row(wp, swq + (S2_ROW + 0) * 4);
#pragma unroll
            for (int p = 0; p < 4; p++) {
                u64 md = pk2(h1[p][0], h1[p][0]);
#pragma unroll
                for (int j = 0; j < 8; j++) acc2[p][j] = ffma2(md, wp[j], bp[j]);
            }
#pragma unroll
            for (int f = 1; f < FEAT; f++) {
                load_row(wp, swq + (S2_ROW + f) * 4);
#pragma unroll
                for (int p = 0; p < 4; p++) {
                    u64 md = pk2(h1[p][f], h1[p][f]);
#pragma unroll
                    for (int j = 0; j < 8; j++) acc2[p][j] = ffma2(md, wp[j], acc2[p][j]);
                }
            }
        }

        // relu -> scalar h2[p][f]
        float h2[4][FEAT];
#pragma unroll
        for (int p = 0; p < 4; p++) {
#pragma unroll
            for (int j = 0; j < 7; j++) {
                float lo, hi; upk2(acc2[p][j], lo, hi);
                h2[p][2 * j]     = fmaxf(lo, 0.f);
                h2[p][2 * j + 1] = fmaxf(hi, 0.f);
            }
            { float lo, hi; upk2(acc2[p][7], lo, hi); h2[p][14] = fmaxf(lo, 0.f); (void)hi; }
        }

        // ---- stage 3: acc3[p][j] = (y[2j], y[2j+1]) ----
        u64 acc3[4][8];
        {
            u64 bp[8]; load_row(bp, swq + (S3_ROW + 15) * 4);
            u64 wp[8];
            load_row(wp, swq + (S3_ROW + 0) * 4);
#pragma unroll
            for (int p = 0; p < 4; p++) {
                u64 md = pk2(h2[p][0], h2[p][0]);
#pragma unroll
                for (int j = 0; j < 8; j++) acc3[p][j] = ffma2(md, wp[j], bp[j]);
            }
#pragma unroll
            for (int f = 1; f < FEAT; f++) {
                load_row(wp, swq + (S3_ROW + f) * 4);
#pragma unroll
                for (int p = 0; p < 4; p++) {
                    u64 md = pk2(h2[p][f], h2[p][f]);
#pragma unroll
                    for (int j = 0; j < 8; j++) acc3[p][j] = ffma2(md, wp[j], acc3[p][j]);
                }
            }
        }

        // ---- store: transpose in-register, one float4 per feature row ----
#pragma unroll
        for (int pp = 0; pp < FEAT; pp++) {
            const int j = pp >> 1;
            float4 st;
            {
                float lo, hi;
                upk2(acc3[0][j], lo, hi); st.x = (pp & 1) ? hi : lo;
                upk2(acc3[1][j], lo, hi); st.y = (pp & 1) ? hi : lo;
                upk2(acc3[2][j], lo, hi); st.z = (pp & 1) ? hi : lo;
                upk2(acc3[3][j], lo, hi); st.w = (pp & 1) ? hi : lo;
            }
            __stcs((float4*)(ob + (size_t)pp * N) + t, st);
        }
    } else {
        // scalar tail for N % 4 leftover points
        const int rem = N & 3;
        const int tp = t - quads;
        if (tp < rem) {
            const int p = (quads << 2) + tp;
            float xv[3] = { xb[p], xb[N + p], xb[2 * (size_t)N + p] };
            float h1[FEAT], h2[FEAT], o[FEAT];
            for (int f = 0; f < FEAT; f++) h1[f] = swf[(S1_ROW + 3) * 16 + f];
            for (int k = 0; k < 3; k++)
                for (int f = 0; f < FEAT; f++)
                    h1[f] += xv[k] * swf[(S1_ROW + k) * 16 + f];
            for (int f = 0; f < FEAT; f++) h1[f] = fmaxf(h1[f], 0.f);

            for (int g = 0; g < FEAT; g++) h2[g] = swf[(S2_ROW + 15) * 16 + g];
            for (int f = 0; f < FEAT; f++)
                for (int g = 0; g < FEAT; g++)
                    h2[g] += h1[f] * swf[(S2_ROW + f) * 16 + g];
            for (int g = 0; g < FEAT; g++) h2[g] = fmaxf(h2[g], 0.f);

            for (int pp = 0; pp < FEAT; pp++) o[pp] = swf[(S3_ROW + 15) * 16 + pp];
            for (int f = 0; f < FEAT; f++)
                for (int pp = 0; pp < FEAT; pp++)
                    o[pp] += h2[f] * swf[(S3_ROW + f) * 16 + pp];
            for (int pp = 0; pp < FEAT; pp++)
                ob[(size_t)pp * N + p] = o[pp];
        }
    }
}

// ---------------------------------------------------------------------------
extern "C" void kernel_launch(void* const* d_in, const int* in_sizes, int n_in,
                              void* d_out, int out_size)
{
    const float* x  = (const float*)d_in[0];
    const float* R  = (const float*)d_in[1];
    const float* W1 = (const float*)d_in[2];
    const float* b1 = (const float*)d_in[3];
    const float* W2 = (const float*)d_in[4];
    const float* b2 = (const float*)d_in[5];
    const float* W3 = (const float*)d_in[6];
    const float* b3 = (const float*)d_in[7];
    const float* Q1 = (const float*)d_in[8];
    const float* Q2 = (const float*)d_in[9];
    const float* Q3 = (const float*)d_in[10];

    int B = in_sizes[1] / 9;
    if (B > MAXB) B = MAXB;
    int N = in_sizes[0] / (3 * B);

    precompute_kernel<<<B, 256>>>(R, W1, b1, W2, b2, W3, b3, Q1, Q2, Q3);

    int quads = N >> 2;
    int gx = (quads + THREADS - 1) / THREADS;
    if (N & 3) gx += 1;   // guarantee spare threads for the scalar tail
    dim3 grid(gx, B);
    mf_main_kernel<<<grid, THREADS>>>(x, (float*)d_out, N);
}

// round 17
// speedup vs baseline: 1.6015x; 1.0430x over previous
#include <cuda_runtime.h>
#include <cuda_bf16.h>

// ---------------------------------------------------------------------------
// ParamMakeFeature: fold rotation into MLP weights, then run a packed-f32x2
// 3->15->15->15 MLP, 4 points per thread.
//
// R7 CORE (validated best): weights stored as SCALARS in smem (4 per
// LDS.128); f32x2 pairs over adjacent FEATURES of one point; weight pairs
// alias loaded float4 registers; 4 pts/thread; float4 I/O with __ldcs/__stcs;
// 128-thr blocks, bounds(128,3), regs~168 structural (caps below ~160 spill:
// R8/R11/R12). PDL (R13/14) and fusion (R15) measured non-wins.
//
// R17: kernel templated on HAS_TAIL. For N%4==0 (the bench shape) the dead
// scalar-tail branch — runtime-indexed local arrays, extra regs, I-cache —
// is deleted at compile time; hot path is straight-line. General N still
// handled by the <true> instantiation.
//
// All hot loops fully unrolled (R4: runtime-indexed arrays demote to local).
// ---------------------------------------------------------------------------

typedef unsigned long long u64;

#define FEAT 15
#define MAXB 32

// per-batch scalar params, 16 floats per row:
//  rows 0-2 : stage1T row k: col f = W1R[f][k]   (col 15 = 0)
//  row  3   : b1[f]
//  rows 4-18: stage2T row f: col g = W2[g][f]    (col 15 = 0)
//  row  19  : b2[g]
//  rows 20-34: stage3T row f: col p = M3[p][f]
//  row  35  : c3[p]
#define S1_ROW 0
#define S2_ROW 4
#define S3_ROW 20
#define PAR_F 576     // 36 rows * 16 floats

__device__ float g_params[MAXB * PAR_F];

__device__ __forceinline__ u64 pk2(float lo, float hi) {
    u64 r; asm("mov.b64 %0, {%1,%2};" : "=l"(r) : "f"(lo), "f"(hi)); return r;
}
__device__ __forceinline__ void upk2(u64 v, float& lo, float& hi) {
    asm("mov.b64 {%0,%1}, %2;" : "=f"(lo), "=f"(hi) : "l"(v));
}
__device__ __forceinline__ u64 ffma2(u64 a, u64 b, u64 c) {
    u64 d; asm("fma.rn.f32x2 %0, %1, %2, %3;" : "=l"(d) : "l"(a), "l"(b), "l"(c));
    return d;
}

// load one 16-float row as 8 feature-pairs (pairs alias the loaded quads)
__device__ __forceinline__ void load_row(u64 wp[8], const float4* q) {
    float4 q0 = q[0], q1 = q[1], q2 = q[2], q3 = q[3];
    wp[0] = pk2(q0.x, q0.y); wp[1] = pk2(q0.z, q0.w);
    wp[2] = pk2(q1.x, q1.y); wp[3] = pk2(q1.z, q1.w);
    wp[4] = pk2(q2.x, q2.y); wp[5] = pk2(q2.z, q2.w);
    wp[6] = pk2(q3.x, q3.y); wp[7] = pk2(q3.z, q3.w);
}

// ---------------------------------------------------------------------------
// Precompute kernel: one block per batch. Builds W1R = W1*R^T, D-blocks,
// M3 = Dblk*W3, c3 = Dblk*b3; writes SCALAR transposed padded layout.
// ---------------------------------------------------------------------------
__global__ void precompute_kernel(
    const float* __restrict__ R_all,
    const float* __restrict__ W1, const float* __restrict__ b1,
    const float* __restrict__ W2, const float* __restrict__ b2,
    const float* __restrict__ W3, const float* __restrict__ b3,
    const float* __restrict__ Q1, const float* __restrict__ Q2,
    const float* __restrict__ Q3)
{
    const int b = blockIdx.x;
    const int tid = threadIdx.x;

    __shared__ float R[9];
    __shared__ float K2[81];
    __shared__ float K3[729];
    __shared__ float E2[9][5];
    __shared__ float E3[27][7];
    __shared__ float D1[3][3], D2[5][5], D3[7][7];
    __shared__ float M3[15][15], c3[15], W1Rs[15][3];

    if (tid < 9) R[tid] = R_all[b * 9 + tid];
    __syncthreads();

    if (tid < 81) {
        int row = tid / 9, col = tid % 9;
        int i = row / 3, k = row % 3, j = col / 3, l = col % 3;
        K2[tid] = R[i * 3 + j] * R[k * 3 + l];
    } else if (tid >= 96 && tid < 105) {
        int t = tid - 96, p = t / 3, q = t % 3;
        float s = 0.f;
        for (int i = 0; i < 3; i++)
            for (int j = 0; j < 3; j++)
                s += Q1[p * 3 + i] * R[i * 3 + j] * Q1[q * 3 + j];
        D1[p][q] = s;
    } else if (tid >= 112 && tid < 157) {
        int t = tid - 112, f = t / 3, j = t % 3;
        float s = 0.f;
        for (int i = 0; i < 3; i++) s += W1[f * 3 + i] * R[j * 3 + i];
        W1Rs[f][j] = s;
    }
    __syncthreads();

    if (tid < 45) {
        int i = tid / 5, q = tid % 5;
        float s = 0.f;
        for (int j = 0; j < 9; j++) s += K2[i * 9 + j] * Q2[q * 9 + j];
        E2[i][q] = s;
    }
    for (int idx = tid; idx < 729; idx += blockDim.x) {
        int row = idx / 27, col = idx % 27;
        int a = row / 3, m = row % 3, bb = col / 3, nn = col % 3;
        K3[idx] = K2[a * 9 + bb] * R[m * 3 + nn];
    }
    __syncthreads();

    if (tid < 25) {
        int p = tid / 5, q = tid % 5;
        float s = 0.f;
        for (int i = 0; i < 9; i++) s += Q2[p * 9 + i] * E2[i][q];
        D2[p][q] = s;
    } else if (tid >= 32 && tid < 32 + 189) {
        int t = tid - 32, u = t / 7, q = t % 7;
        float s = 0.f;
        for (int v = 0; v < 27; v++) s += K3[u * 27 + v] * Q3[q * 27 + v];
        E3[u][q] = s;
    }
    __syncthreads();

    if (tid < 49) {
        int p = tid / 7, q = tid % 7;
        float s = 0.f;
        for (int u = 0; u < 27; u++) s += Q3[p * 27 + u] * E3[u][q];
        D3[p][q] = s;
    }
    __syncthreads();

    if (tid < 225) {
        int p = tid / 15, f = tid % 15;
        float s = 0.f;
        if (p < 3)       { for (int q = 0; q < 3; q++) s += D1[p][q]     * W3[q * 15 + f]; }
        else if (p < 8)  { for (int q = 0; q < 5; q++) s += D2[p - 3][q] * W3[(3 + q) * 15 + f]; }
        else             { for (int q = 0; q < 7; q++) s += D3[p - 8][q] * W3[(8 + q) * 15 + f]; }
        M3[p][f] = s;
    } else if (tid < 240) {
        int p = tid - 225;
        float s = 0.f;
        if (p < 3)       { for (int q = 0; q < 3; q++) s += D1[p][q]     * b3[q]; }
        else if (p < 8)  { for (int q = 0; q < 5; q++) s += D2[p - 3][q] * b3[3 + q]; }
        else             { for (int q = 0; q < 7; q++) s += D3[p - 8][q] * b3[8 + q]; }
        c3[p] = s;
    }
    __syncthreads();

    // write scalar transposed padded layout
    float* dst = g_params + (size_t)b * PAR_F;
    for (int idx = tid; idx < PAR_F; idx += blockDim.x) {
        float v = 0.f;
        if (idx < S2_ROW * 16) {
            int k = idx >> 4, f = idx & 15;
            if (f < 15) v = (k < 3) ? W1Rs[f][k] : b1[f];
        } else if (idx < S3_ROW * 16) {
            int r = idx - S2_ROW * 16, f = r >> 4, g = r & 15;
            if (g < 15) v = (f < 15) ? W2[g * 15 + f] : b2[g];
        } else {
            int r = idx - S3_ROW * 16, f = r >> 4, p = r & 15;
            if (p < 15) v = (f < 15) ? M3[p][f] : c3[p];
        }
        dst[idx] = v;
    }
}

// ---------------------------------------------------------------------------
// Main kernel: 4 points per thread, feature-paired f32x2 accumulators.
// HAS_TAIL=false (N%4==0): scalar-tail branch deleted at compile time.
// ---------------------------------------------------------------------------
#define THREADS 128

template <bool HAS_TAIL>
__global__ __launch_bounds__(THREADS, 3)
void mf_main_kernel(const float* __restrict__ x, float* __restrict__ out, int N)
{
    const int b = blockIdx.y;
    __shared__ __align__(16) float swf[PAR_F];
    {
        const float4* src = (const float4*)(g_params + (size_t)b * PAR_F);
        float4* dstq = (float4*)swf;
        for (int i = threadIdx.x; i < PAR_F / 4; i += THREADS) dstq[i] = src[i];
    }
    __syncthreads();

    const int t = blockIdx.x * THREADS + threadIdx.x;
    const int quads = N >> 2;

    const float* xb = x + (size_t)b * 3 * N;
    float* __restrict__ ob = out + (size_t)b * FEAT * N;
    const float4* swq = (const float4*)swf;

    if (t < quads) {
        float4 a0 = __ldcs((const float4*)(xb                 ) + t);
        float4 a1 = __ldcs((const float4*)(xb + N             ) + t);
        float4 a2 = __ldcs((const float4*)(xb + 2 * (size_t)N ) + t);
        float xc0[4] = { a0.x, a0.y, a0.z, a0.w };
        float xc1[4] = { a1.x, a1.y, a1.z, a1.w };
        float xc2[4] = { a2.x, a2.y, a2.z, a2.w };

        // ---- stage 1: acc[p][j] = (h1[2j], h1[2j+1]) ----
        u64 acc1[4][8];
        {
            u64 bp[8]; load_row(bp, swq + (S1_ROW + 3) * 4);
            u64 wp[8];
            load_row(wp, swq + (S1_ROW + 0) * 4);
#pragma unroll
            for (int p = 0; p < 4; p++) {
                u64 xd = pk2(xc0[p], xc0[p]);
#pragma unroll
                for (int j = 0; j < 8; j++) acc1[p][j] = ffma2(xd, wp[j], bp[j]);
            }
            load_row(wp, swq + (S1_ROW + 1) * 4);
#pragma unroll
            for (int p = 0; p < 4; p++) {
                u64 xd = pk2(xc1[p], xc1[p]);
#pragma unroll
                for (int j = 0; j < 8; j++) acc1[p][j] = ffma2(xd, wp[j], acc1[p][j]);
            }
            load_row(wp, swq + (S1_ROW + 2) * 4);
#pragma unroll
            for (int p = 0; p < 4; p++) {
                u64 xd = pk2(xc2[p], xc2[p]);
#pragma unroll
                for (int j = 0; j < 8; j++) acc1[p][j] = ffma2(xd, wp[j], acc1[p][j]);
            }
        }

        // relu -> scalar h1[p][f]
        float h1[4][FEAT];
#pragma unroll
        for (int p = 0; p < 4; p++) {
#pragma unroll
            for (int j = 0; j < 7; j++) {
                float lo, hi; upk2(acc1[p][j], lo, hi);
                h1[p][2 * j]     = fmaxf(lo, 0.f);
                h1[p][2 * j + 1] = fmaxf(hi, 0.f);
            }
            { float lo, hi; upk2(acc1[p][7], lo, hi); h1[p][14] = fmaxf(lo, 0.f); (void)hi; }
        }

        // ---- stage 2: acc2[p][j] = (h2[2j], h2[2j+1]) ----
        u64 acc2[4][8];
        {
            u64 bp[8]; load_row(bp, swq + (S2_ROW + 15) * 4);
            u64 wp[8];
            load_row(wp, swq + (S2_ROW + 0) * 4);
#pragma unroll
            for (int p = 0; p < 4; p++) {
                u64 md = pk2(h1[p][0], h1[p][0]);
#pragma unroll
                for (int j = 0; j < 8; j++) acc2[p][j] = ffma2(md, wp[j], bp[j]);
            }
#pragma unroll
            for (int f = 1; f < FEAT; f++) {
                load_row(wp, swq + (S2_ROW + f) * 4);
#pragma unroll
                for (int p = 0; p < 4; p++) {
                    u64 md = pk2(h1[p][f], h1[p][f]);
#pragma unroll
                    for (int j = 0; j < 8; j++) acc2[p][j] = ffma2(md, wp[j], acc2[p][j]);
                }
            }
        }

        // relu -> scalar h2[p][f]
        float h2[4][FEAT];
#pragma unroll
        for (int p = 0; p < 4; p++) {
#pragma unroll
            for (int j = 0; j < 7; j++) {
                float lo, hi; upk2(acc2[p][j], lo, hi);
                h2[p][2 * j]     = fmaxf(lo, 0.f);
                h2[p][2 * j + 1] = fmaxf(hi, 0.f);
            }
            { float lo, hi; upk2(acc2[p][7], lo, hi); h2[p][14] = fmaxf(lo, 0.f); (void)hi; }
        }

        // ---- stage 3: acc3[p][j] = (y[2j], y[2j+1]) ----
        u64 acc3[4][8];
        {
            u64 bp[8]; load_row(bp, swq + (S3_ROW + 15) * 4);
            u64 wp[8];
            load_row(wp, swq + (S3_ROW + 0) * 4);
#pragma unroll
            for (int p = 0; p < 4; p++) {
                u64 md = pk2(h2[p][0], h2[p][0]);
#pragma unroll
                for (int j = 0; j < 8; j++) acc3[p][j] = ffma2(md, wp[j], bp[j]);
            }
#pragma unroll
            for (int f = 1; f < FEAT; f++) {
                load_row(wp, swq + (S3_ROW + f) * 4);
#pragma unroll
                for (int p = 0; p < 4; p++) {
                    u64 md = pk2(h2[p][f], h2[p][f]);
#pragma unroll
                    for (int j = 0; j < 8; j++) acc3[p][j] = ffma2(md, wp[j], acc3[p][j]);
                }
            }
        }

        // ---- store: transpose in-register, one float4 per feature row ----
#pragma unroll
        for (int pp = 0; pp < FEAT; pp++) {
            const int j = pp >> 1;
            float4 st;
            {
                float lo, hi;
                upk2(acc3[0][j], lo, hi); st.x = (pp & 1) ? hi : lo;
                upk2(acc3[1][j], lo, hi); st.y = (pp & 1) ? hi : lo;
                upk2(acc3[2][j], lo, hi); st.z = (pp & 1) ? hi : lo;
                upk2(acc3[3][j], lo, hi); st.w = (pp & 1) ? hi : lo;
            }
            __stcs((float4*)(ob + (size_t)pp * N) + t, st);
        }
    } else if (HAS_TAIL) {
        // scalar tail for N % 4 leftover points (compiled out when !HAS_TAIL)
        const int rem = N & 3;
        const int tp = t - quads;
        if (tp < rem) {
            const int p = (quads << 2) + tp;
            float xv[3] = { xb[p], xb[N + p], xb[2 * (size_t)N + p] };
            float h1[FEAT], h2[FEAT], o[FEAT];
            for (int f = 0; f < FEAT; f++) h1[f] = swf[(S1_ROW + 3) * 16 + f];
            for (int k = 0; k < 3; k++)
                for (int f = 0; f < FEAT; f++)
                    h1[f] += xv[k] * swf[(S1_ROW + k) * 16 + f];
            for (int f = 0; f < FEAT; f++) h1[f] = fmaxf(h1[f], 0.f);

            for (int g = 0; g < FEAT; g++) h2[g] = swf[(S2_ROW + 15) * 16 + g];
            for (int f = 0; f < FEAT; f++)
                for (int g = 0; g < FEAT; g++)
                    h2[g] += h1[f] * swf[(S2_ROW + f) * 16 + g];
            for (int g = 0; g < FEAT; g++) h2[g] = fmaxf(h2[g], 0.f);

            for (int pp = 0; pp < FEAT; pp++) o[pp] = swf[(S3_ROW + 15) * 16 + pp];
            for (int f = 0; f < FEAT; f++)
                for (int pp = 0; pp < FEAT; pp++)
                    o[pp] += h2[f] * swf[(S3_ROW + f) * 16 + pp];
            for (int pp = 0; pp < FEAT; pp++)
                ob[(size_t)pp * N + p] = o[pp];
        }
    }
}

// ---------------------------------------------------------------------------
extern "C" void kernel_launch(void* const* d_in, const int* in_sizes, int n_in,
                              void* d_out, int out_size)
{
    const float* x  = (const float*)d_in[0];
    const float* R  = (const float*)d_in[1];
    const float* W1 = (const float*)d_in[2];
    const float* b1 = (const float*)d_in[3];
    const float* W2 = (const float*)d_in[4];
    const float* b2 = (const float*)d_in[5];
    const float* W3 = (const float*)d_in[6];
    const float* b3 = (const float*)d_in[7];
    const float* Q1 = (const float*)d_in[8];
    const float* Q2 = (const float*)d_in[9];
    const float* Q3 = (const float*)d_in[10];

    int B = in_sizes[1] / 9;
    if (B > MAXB) B = MAXB;
    int N = in_sizes[0] / (3 * B);

    precompute_kernel<<<B, 256>>>(R, W1, b1, W2, b2, W3, b3, Q1, Q2, Q3);

    int quads = N >> 2;
    if ((N & 3) == 0) {
        int gx = (quads + THREADS - 1) / THREADS;
        dim3 grid(gx, B);
        mf_main_kernel<false><<<grid, THREADS>>>(x, (float*)d_out, N);
    } else {
        int gx = (quads + THREADS - 1) / THREADS + 1;  // spare block for tail
        dim3 grid(gx, B);
        mf_main_kernel<true><<<grid, THREADS>>>(x, (float*)d_out, N);
    }
}